// round 6
// baseline (speedup 1.0000x reference)
#include <cuda_runtime.h>
#include <cstdint>

#define EMB 256
#define HID 64
#define MAXN 100000
#define MAXQ 8192

// ---------------- scratch (device globals; no allocation) ----------------
__device__ int   g_slot[MAXN];           // node -> compact slot (query index) or -1
__device__ float g_s[MAXQ * EMB];        // per-slot aggregated sum_e w_e * emb[src_e]
__device__ float g_c[MAXQ];              // per-slot sum_e w_e
__device__ float g_part[2][MAXQ][HID];   // per-half pre-activation partials

// ---------------- setup kernels ----------------
__global__ void k_init_slot(int n_nodes) {
    int i = blockIdx.x * blockDim.x + threadIdx.x;
    if (i < n_nodes) g_slot[i] = -1;
}

__global__ void k_mark_zero(const int* __restrict__ query, int Q) {
    int i = blockIdx.x * blockDim.x + threadIdx.x;
    if (i < MAXQ * EMB / 4) ((float4*)g_s)[i] = make_float4(0.f, 0.f, 0.f, 0.f);
    if (i < MAXQ)           g_c[i] = 0.0f;
    if (i < Q)              atomicCAS(&g_slot[query[i]], -1, i);
}

__device__ __forceinline__ float4 scale4(float4 v, float w) {
    return make_float4(v.x * w, v.y * w, v.z * w, v.w * w);
}

// Fused filter + scatter: warp scans 32 edges, ballots hits (~8.2%), processes
// hits two at a time with full-warp gathers and vector RED into g_s.
__global__ void __launch_bounds__(256) k_scatter_fused(
    const int* __restrict__ src, const int* __restrict__ dst,
    const float* __restrict__ ew, const float* __restrict__ emb, int E)
{
    int lane = threadIdx.x & 31;
    int gw   = (blockIdx.x * blockDim.x + threadIdx.x) >> 5;
    int nw   = (gridDim.x * blockDim.x) >> 5;

    for (int base = gw * 32; base < E; base += nw * 32) {
        int  e = base + lane;
        bool v = (e < E);
        int   d_n = v ? dst[e] : 0;
        int   s_n = v ? src[e] : 0;
        float w   = v ? ew[e]  : 0.f;
        int   sl  = v ? g_slot[d_n] : -1;
        unsigned mask = __ballot_sync(0xffffffffu, sl >= 0);

        while (mask) {
            int b0 = __ffs(mask) - 1; mask &= mask - 1;
            int b1 = -1;
            if (mask) { b1 = __ffs(mask) - 1; mask &= mask - 1; }
            int bb1 = (b1 < 0) ? b0 : b1;

            int   sn0 = __shfl_sync(0xffffffffu, s_n, b0);
            int   sl0 = __shfl_sync(0xffffffffu, sl,  b0);
            float w0  = __shfl_sync(0xffffffffu, w,   b0);
            int   sn1 = __shfl_sync(0xffffffffu, s_n, bb1);
            int   sl1 = __shfl_sync(0xffffffffu, sl,  bb1);
            float w1  = __shfl_sync(0xffffffffu, w,   bb1);

            const float4* r0 = (const float4*)(emb + (size_t)sn0 * EMB);
            const float4* r1 = (const float4*)(emb + (size_t)sn1 * EMB);
            float4 a0 = r0[lane], c0 = r0[lane + 32];
            float4 a1, c1;
            if (b1 >= 0) { a1 = r1[lane]; c1 = r1[lane + 32]; }

            float4* s0 = (float4*)(g_s + (size_t)sl0 * EMB);
            atomicAdd(&s0[lane],      scale4(a0, w0));
            atomicAdd(&s0[lane + 32], scale4(c0, w0));
            if (b1 >= 0) {
                float4* s1 = (float4*)(g_s + (size_t)sl1 * EMB);
                atomicAdd(&s1[lane],      scale4(a1, w1));
                atomicAdd(&s1[lane + 32], scale4(c1, w1));
            }
            if (lane == 0) {
                atomicAdd(&g_c[sl0], w0);
                if (b1 >= 0) atomicAdd(&g_c[sl1], w1);
            }
        }
    }
}

// ---------------- readout part 1: per-half partial GEMM ----------------
// Block = 128 threads (4 warps), handles (32 q) x (64 o) x (256 k) for one
// half: h=0 -> Ws @ emb[node], h=1 -> Wn @ g_s[slot]. grid = 2 * Q/32.
// Thread tile 4q x 4o via 8x fma.rn.f32x2. Partials -> g_part[h][q][o].
#define QB    32
#define KSUB  128
#define WROW  68                    // 64 o + pad  (272 B row)
#define GROW  36                    // 32 q + pad  (144 B row)
#define WBF   0
#define GBF   (KSUB * WROW)
#define AUXF  (GBF + KSUB * GROW)
#define RH_SMEM ((AUXF + 32) * 4)

__global__ void __launch_bounds__(128) k_half(
    const float* __restrict__ emb, const float* __restrict__ Ws,
    const float* __restrict__ Wn,  const int* __restrict__ query, int Q)
{
    extern __shared__ float sm[];
    float* wbuf = sm + WBF;                   // [KSUB][WROW]  k-major, o contiguous
    float* gbuf = sm + GBF;                   // [KSUB][GROW]  k-major, q contiguous
    int*   rows = (int*)(sm + AUXF);          // [32] node or slot index

    int tid   = threadIdx.x;
    int h     = blockIdx.x & 1;               // 0: self (Ws,emb)  1: neigh (Wn,g_s)
    int qt    = blockIdx.x >> 1;
    int qbase = qt * QB;

    if (tid < QB) {
        int q = qbase + tid;
        int node = (q < Q) ? query[q] : query[0];
        rows[tid] = h ? g_slot[node] : node;
    }
    __syncthreads();

    int lane  = tid & 31;
    int wl    = tid >> 5;           // 0..3
    int o_idx = lane & 15;          // o = 4*o_idx .. +3
    int q_idx = lane >> 4;
    int qloc  = wl * 8 + q_idx * 4; // q = qloc .. qloc+3 (block-local)

    const float* W    = h ? Wn : Ws;
    const float* abase = h ? g_s : emb;

    uint32_t smem_u32;
    asm("{ .reg .u64 t; cvta.to.shared.u64 t, %1; cvt.u32.u64 %0, t; }"
        : "=r"(smem_u32) : "l"(sm));

    unsigned long long a00 = 0, a01 = 0, a10 = 0, a11 = 0;
    unsigned long long a20 = 0, a21 = 0, a30 = 0, a31 = 0;

#define FMA2(ACC, WV, GV) \
    asm("fma.rn.f32x2 %0, %1, %2, %0;" : "+l"(ACC) : "l"(WV), "l"(GV))

#define KSTEP(IMM, FOFF) { \
    unsigned long long wv0, wv1; \
    asm volatile("ld.shared.v2.b64 {%0, %1}, [%2+" IMM "];" \
                 : "=l"(wv0), "=l"(wv1) : "r"(wb)); \
    float4 gv = *(const float4*)(gp + (FOFF)); \
    uint32_t ux = __float_as_uint(gv.x), uy = __float_as_uint(gv.y); \
    uint32_t uz = __float_as_uint(gv.z), uw = __float_as_uint(gv.w); \
    unsigned long long g0, g1, g2, g3; \
    asm("mov.b64 %0, {%1, %1};" : "=l"(g0) : "r"(ux)); \
    asm("mov.b64 %0, {%1, %1};" : "=l"(g1) : "r"(uy)); \
    asm("mov.b64 %0, {%1, %1};" : "=l"(g2) : "r"(uz)); \
    asm("mov.b64 %0, {%1, %1};" : "=l"(g3) : "r"(uw)); \
    FMA2(a00, wv0, g0); FMA2(a01, wv1, g0); \
    FMA2(a10, wv0, g1); FMA2(a11, wv1, g1); \
    FMA2(a20, wv0, g2); FMA2(a21, wv1, g2); \
    FMA2(a30, wv0, g3); FMA2(a31, wv1, g3); }

    for (int sc = 0; sc < 2; ++sc) {
        int kc = sc * KSUB;         // k offset within this half's 256
        // Stage weights transposed: wbuf[k][o] = W[o][kc+k]
        for (int it = 0; it < 16; ++it) {
            int idx = tid + it * 128;               // 2048 float4 items
            int o  = idx & 63;
            int kb = idx >> 6;                      // 0..31
            float4 v = *(const float4*)&W[o * EMB + kc + 4 * kb];
            float* b = wbuf + (4 * kb) * WROW + o;  // conflict-free STS
            b[0] = v.x; b[WROW] = v.y; b[2 * WROW] = v.z; b[3 * WROW] = v.w;
        }
        // Stage activations transposed: gbuf[k][q] = row_q[kc+k]
        for (int it = 0; it < 8; ++it) {
            int idx = tid + it * 128;               // 1024 float4 items
            int q  = idx & 31;
            int kb = idx >> 5;                      // 0..31
            const float* row = abase + (size_t)rows[q] * EMB;
            float4 v = ((const float4*)row)[(kc >> 2) + kb];
            float* b = gbuf + (4 * kb) * GROW + q;  // conflict-free STS
            b[0] = v.x; b[GROW] = v.y; b[2 * GROW] = v.z; b[3 * GROW] = v.w;
        }
        __syncthreads();

        uint32_t wb = smem_u32 + (uint32_t)(WBF + 4 * o_idx) * 4u;
        const float* gp = sm + GBF + qloc;
#pragma unroll 1
        for (int k4 = 0; k4 < KSUB / 4; ++k4) {
            KSTEP("0",   0)
            KSTEP("272", GROW)
            KSTEP("544", 2 * GROW)
            KSTEP("816", 3 * GROW)
            wb += 1088;             // 4 * WROW floats
            gp += 4 * GROW;
        }
        __syncthreads();
    }

    // Write partials: g_part[h][q][4*o_idx .. +3]
    unsigned long long pa[4][2] = {{a00, a01}, {a10, a11}, {a20, a21}, {a30, a31}};
#pragma unroll
    for (int qi = 0; qi < 4; ++qi) {
        int q = qbase + qloc + qi;
        if (q < Q) {
            float4 v;
            v.x = __uint_as_float((uint32_t)pa[qi][0]);
            v.y = __uint_as_float((uint32_t)(pa[qi][0] >> 32));
            v.z = __uint_as_float((uint32_t)pa[qi][1]);
            v.w = __uint_as_float((uint32_t)(pa[qi][1] >> 32));
            *(float4*)&g_part[h][q][4 * o_idx] = v;
        }
    }
}

// ---------------- readout part 2: combine + epilogue ----------------
// Warp per query: x = p0 + p1 + bs + c*bn ; out = Wr . relu(x) + br
__global__ void __launch_bounds__(256) k_combine(
    const float* __restrict__ bs, const float* __restrict__ bn,
    const float* __restrict__ Wr, const float* __restrict__ br,
    const int* __restrict__ query, float* __restrict__ out, int Q)
{
    int q    = blockIdx.x * 8 + (threadIdx.x >> 5);
    int lane = threadIdx.x & 31;
    if (q >= Q) return;

    float2 p0 = *(const float2*)&g_part[0][q][2 * lane];
    float2 p1 = *(const float2*)&g_part[1][q][2 * lane];
    float  cc = g_c[g_slot[query[q]]];
    float2 b1 = *(const float2*)&bs[2 * lane];
    float2 b2 = *(const float2*)&bn[2 * lane];
    float2 wr = *(const float2*)&Wr[2 * lane];

    float x0 = fmaxf(p0.x + p1.x + b1.x + cc * b2.x, 0.f);
    float x1 = fmaxf(p0.y + p1.y + b1.y + cc * b2.y, 0.f);
    float r  = wr.x * x0 + wr.y * x1;
#pragma unroll
    for (int off = 16; off > 0; off >>= 1) r += __shfl_xor_sync(0xffffffffu, r, off);
    if (lane == 0) out[q] = r + br[0];
}

// ---------------- launch ----------------
extern "C" void kernel_launch(void* const* d_in, const int* in_sizes, int n_in,
                              void* d_out, int out_size) {
    const float* emb = (const float*)d_in[0];
    const float* ew  = (const float*)d_in[1];
    const float* Ws  = (const float*)d_in[2];
    const float* bs  = (const float*)d_in[3];
    const float* Wn  = (const float*)d_in[4];
    const float* bn  = (const float*)d_in[5];
    const float* Wr  = (const float*)d_in[6];
    const float* br  = (const float*)d_in[7];
    const int*   src = (const int*)d_in[8];
    const int*   dst = (const int*)d_in[9];
    const int*   qry = (const int*)d_in[10];

    int N = in_sizes[0] / EMB;
    int E = in_sizes[8];
    int Q = in_sizes[10];

    cudaFuncSetAttribute(k_half, cudaFuncAttributeMaxDynamicSharedMemorySize, RH_SMEM);

    int qtiles = (Q + QB - 1) / QB;
    k_init_slot    <<<(N + 255) / 256, 256>>>(N);
    k_mark_zero    <<<(MAXQ * EMB / 4 + 255) / 256, 256>>>(qry, Q);
    k_scatter_fused<<<1184, 256>>>(src, dst, ew, emb, E);
    k_half         <<<2 * qtiles, 128, RH_SMEM>>>(emb, Ws, Wn, qry, Q);
    k_combine      <<<(Q + 7) / 8, 256>>>(bs, bn, Wr, br, qry, (float*)d_out, Q);
}

// round 7
// speedup vs baseline: 1.5549x; 1.5549x over previous
#include <cuda_runtime.h>
#include <cstdint>

#define EMB 256
#define HID 64
#define MAXN 100000
#define MAXQ 8192

// ---------------- scratch (device globals; no allocation) ----------------
__device__ int   g_slot[MAXN];        // node -> compact slot (query index) or -1
__device__ float g_s[MAXQ * EMB];     // per-slot aggregated sum_e w_e * emb[src_e]
__device__ float g_c[MAXQ];           // per-slot sum_e w_e

// ---------------- setup kernels ----------------
__global__ void k_init_slot(int n_nodes) {
    int i = blockIdx.x * blockDim.x + threadIdx.x;
    if (i < n_nodes) g_slot[i] = -1;
}

__global__ void k_mark_zero(const int* __restrict__ query, int Q) {
    int i = blockIdx.x * blockDim.x + threadIdx.x;
    if (i < MAXQ * EMB / 4) ((float4*)g_s)[i] = make_float4(0.f, 0.f, 0.f, 0.f);
    if (i < MAXQ)           g_c[i] = 0.0f;
    if (i < Q)              atomicCAS(&g_slot[query[i]], -1, i);
}

__device__ __forceinline__ float4 scale4(float4 v, float w) {
    return make_float4(v.x * w, v.y * w, v.z * w, v.w * w);
}

// Fused filter + scatter: warp scans 32 edges, ballots hits (~8.2%), processes
// hits two at a time with full-warp gathers and vector RED into g_s.
__global__ void __launch_bounds__(256) k_scatter_fused(
    const int* __restrict__ src, const int* __restrict__ dst,
    const float* __restrict__ ew, const float* __restrict__ emb, int E)
{
    int lane = threadIdx.x & 31;
    int gw   = (blockIdx.x * blockDim.x + threadIdx.x) >> 5;
    int nw   = (gridDim.x * blockDim.x) >> 5;

    for (int base = gw * 32; base < E; base += nw * 32) {
        int  e = base + lane;
        bool v = (e < E);
        int   d_n = v ? dst[e] : 0;
        int   s_n = v ? src[e] : 0;
        float w   = v ? ew[e]  : 0.f;
        int   sl  = v ? g_slot[d_n] : -1;
        unsigned mask = __ballot_sync(0xffffffffu, sl >= 0);

        while (mask) {
            int b0 = __ffs(mask) - 1; mask &= mask - 1;
            int b1 = -1;
            if (mask) { b1 = __ffs(mask) - 1; mask &= mask - 1; }
            int bb1 = (b1 < 0) ? b0 : b1;

            int   sn0 = __shfl_sync(0xffffffffu, s_n, b0);
            int   sl0 = __shfl_sync(0xffffffffu, sl,  b0);
            float w0  = __shfl_sync(0xffffffffu, w,   b0);
            int   sn1 = __shfl_sync(0xffffffffu, s_n, bb1);
            int   sl1 = __shfl_sync(0xffffffffu, sl,  bb1);
            float w1  = __shfl_sync(0xffffffffu, w,   bb1);

            const float4* r0 = (const float4*)(emb + (size_t)sn0 * EMB);
            const float4* r1 = (const float4*)(emb + (size_t)sn1 * EMB);
            float4 a0 = r0[lane], c0 = r0[lane + 32];
            float4 a1, c1;
            if (b1 >= 0) { a1 = r1[lane]; c1 = r1[lane + 32]; }

            float4* s0 = (float4*)(g_s + (size_t)sl0 * EMB);
            atomicAdd(&s0[lane],      scale4(a0, w0));
            atomicAdd(&s0[lane + 32], scale4(c0, w0));
            if (b1 >= 0) {
                float4* s1 = (float4*)(g_s + (size_t)sl1 * EMB);
                atomicAdd(&s1[lane],      scale4(a1, w1));
                atomicAdd(&s1[lane + 32], scale4(c1, w1));
            }
            if (lane == 0) {
                atomicAdd(&g_c[sl0], w0);
                if (b1 >= 0) atomicAdd(&g_c[sl1], w1);
            }
        }
    }
}

// ---------------- tensor-core readout ----------------
// out[q] = Wr . relu(Ws@emb[node_q] + Wn@s[slot_q] + bs + c_q*bn) + br
// [32q x 64o] block tile, K=512 (chunks 0-3: Ws/emb, 4-7: Wn/g_s), 64 k per
// chunk, cp.async double-buffered. mma.sync.m16n8k8.tf32 with cvt.rna.
#define QT     32
#define KCH    64
#define AROW   68                       // 272 B row, 16B aligned, CF frag loads
#define ABUF   (QT * AROW)              // 2176 floats per A buffer
#define BBUF   (HID * AROW)             // 4352 floats per B buffer
#define ASM_O  0
#define BSM_O  (2 * ABUF)
#define AUX_O  (BSM_O + 2 * BBUF)       // nodes[32] slots[32] csm[32] rsum[2][32]
#define RM_SMEM ((AUX_O + 160) * 4)

__device__ __forceinline__ uint32_t f2tf32(float x) {
    uint32_t r;
    asm("cvt.rna.tf32.f32 %0, %1;" : "=r"(r) : "f"(x));
    return r;
}

__global__ void __launch_bounds__(128) k_readout_mma(
    const float* __restrict__ emb, const float* __restrict__ Ws,
    const float* __restrict__ Wn,  const float* __restrict__ bs,
    const float* __restrict__ bn,  const float* __restrict__ Wr,
    const float* __restrict__ br,  const int* __restrict__ query,
    float* __restrict__ out, int Q)
{
    extern __shared__ float sm[];
    int*   nodes = (int*)(sm + AUX_O);
    int*   slots = nodes + QT;
    float* csm   = (float*)(slots + QT);
    float* rsum  = csm + QT;               // [2][QT]

    int tid   = threadIdx.x;
    int qbase = blockIdx.x * QT;

    if (tid < QT) {
        int q = qbase + tid;
        int node = (q < Q) ? query[q] : query[0];
        nodes[tid] = node;
        int sl = g_slot[node];
        slots[tid] = sl;
        csm[tid] = g_c[sl];
    }
    __syncthreads();

    uint32_t smem_u32;
    asm("{ .reg .u64 t; cvta.to.shared.u64 t, %1; cvt.u32.u64 %0, t; }"
        : "=r"(smem_u32) : "l"(sm));

#define STAGE(C, B) { \
    int kc = ((C) & 3) * KCH; \
    _Pragma("unroll") \
    for (int it = 0; it < 4; ++it) { \
        int idx = tid + it * 128, row = idx >> 4, c4 = idx & 15; \
        const float* rb = ((C) < 4) ? emb + (size_t)nodes[row] * EMB \
                                    : g_s + (size_t)slots[row] * EMB; \
        const float* srcp = rb + kc + c4 * 4; \
        uint32_t dstp = smem_u32 + (uint32_t)(ASM_O + (B) * ABUF + row * AROW + c4 * 4) * 4u; \
        asm volatile("cp.async.cg.shared.global [%0], [%1], 16;" :: "r"(dstp), "l"(srcp)); \
    } \
    const float* W = ((C) < 4) ? Ws : Wn; \
    _Pragma("unroll") \
    for (int it = 0; it < 8; ++it) { \
        int idx = tid + it * 128, o = idx >> 4, c4 = idx & 15; \
        const float* srcp = W + o * EMB + kc + c4 * 4; \
        uint32_t dstp = smem_u32 + (uint32_t)(BSM_O + (B) * BBUF + o * AROW + c4 * 4) * 4u; \
        asm volatile("cp.async.cg.shared.global [%0], [%1], 16;" :: "r"(dstp), "l"(srcp)); \
    } \
    asm volatile("cp.async.commit_group;"); }

    int lane = tid & 31;
    int w    = tid >> 5;
    int wm   = w >> 1, wn = w & 1;       // warp tile: m16 x n32
    int g    = lane >> 2, t = lane & 3;

    float acc[4][4];
#pragma unroll
    for (int a = 0; a < 4; ++a)
#pragma unroll
        for (int b = 0; b < 4; ++b) acc[a][b] = 0.f;

    STAGE(0, 0)

#pragma unroll
    for (int c = 0; c < 8; ++c) {
        if (c < 7) STAGE(c + 1, (c + 1) & 1)
        if (c < 7) { asm volatile("cp.async.wait_group 1;"); }
        else       { asm volatile("cp.async.wait_group 0;"); }
        __syncthreads();

        const float* ab = sm + ASM_O + (c & 1) * ABUF + (wm * 16 + g) * AROW + t;
        const float* bb = sm + BSM_O + (c & 1) * BBUF + (wn * 32 + g) * AROW + t;
#pragma unroll
        for (int ks = 0; ks < 8; ++ks) {
            int k0 = ks * 8;
            uint32_t a0 = f2tf32(ab[k0]);
            uint32_t a1 = f2tf32(ab[k0 + 8 * AROW]);
            uint32_t a2 = f2tf32(ab[k0 + 4]);
            uint32_t a3 = f2tf32(ab[k0 + 8 * AROW + 4]);
#pragma unroll
            for (int nt = 0; nt < 4; ++nt) {
                uint32_t b0 = f2tf32(bb[k0 + nt * 8 * AROW]);
                uint32_t b1 = f2tf32(bb[k0 + nt * 8 * AROW + 4]);
                asm("mma.sync.aligned.m16n8k8.row.col.f32.tf32.tf32.f32 "
                    "{%0,%1,%2,%3}, {%4,%5,%6,%7}, {%8,%9}, {%0,%1,%2,%3};"
                    : "+f"(acc[nt][0]), "+f"(acc[nt][1]),
                      "+f"(acc[nt][2]), "+f"(acc[nt][3])
                    : "r"(a0), "r"(a1), "r"(a2), "r"(a3), "r"(b0), "r"(b1));
            }
        }
        __syncthreads();
    }

    // Epilogue: rows q = wm*16 + g (+8), cols o = wn*32 + nt*8 + 2t (+1)
    int qr0 = wm * 16 + g, qr1 = qr0 + 8;
    float cc0 = csm[qr0], cc1 = csm[qr1];
    float l0 = 0.f, l1 = 0.f;
#pragma unroll
    for (int nt = 0; nt < 4; ++nt) {
        int o0 = wn * 32 + nt * 8 + 2 * t;
        float b_s0 = bs[o0], b_s1 = bs[o0 + 1];
        float b_n0 = bn[o0], b_n1 = bn[o0 + 1];
        float w_r0 = Wr[o0], w_r1 = Wr[o0 + 1];
        l0 += w_r0 * fmaxf(acc[nt][0] + b_s0 + cc0 * b_n0, 0.f)
            + w_r1 * fmaxf(acc[nt][1] + b_s1 + cc0 * b_n1, 0.f);
        l1 += w_r0 * fmaxf(acc[nt][2] + b_s0 + cc1 * b_n0, 0.f)
            + w_r1 * fmaxf(acc[nt][3] + b_s1 + cc1 * b_n1, 0.f);
    }
    l0 += __shfl_xor_sync(0xffffffffu, l0, 1);
    l0 += __shfl_xor_sync(0xffffffffu, l0, 2);
    l1 += __shfl_xor_sync(0xffffffffu, l1, 1);
    l1 += __shfl_xor_sync(0xffffffffu, l1, 2);
    if (t == 0) {
        rsum[wn * QT + qr0] = l0;
        rsum[wn * QT + qr1] = l1;
    }
    __syncthreads();
    if (tid < QT) {
        int q = qbase + tid;
        if (q < Q) out[q] = rsum[tid] + rsum[QT + tid] + br[0];
    }
}

// ---------------- launch ----------------
extern "C" void kernel_launch(void* const* d_in, const int* in_sizes, int n_in,
                              void* d_out, int out_size) {
    const float* emb = (const float*)d_in[0];
    const float* ew  = (const float*)d_in[1];
    const float* Ws  = (const float*)d_in[2];
    const float* bs  = (const float*)d_in[3];
    const float* Wn  = (const float*)d_in[4];
    const float* bn  = (const float*)d_in[5];
    const float* Wr  = (const float*)d_in[6];
    const float* br  = (const float*)d_in[7];
    const int*   src = (const int*)d_in[8];
    const int*   dst = (const int*)d_in[9];
    const int*   qry = (const int*)d_in[10];

    int N = in_sizes[0] / EMB;
    int E = in_sizes[8];
    int Q = in_sizes[10];

    cudaFuncSetAttribute(k_readout_mma, cudaFuncAttributeMaxDynamicSharedMemorySize, RM_SMEM);

    k_init_slot    <<<(N + 255) / 256, 256>>>(N);
    k_mark_zero    <<<(MAXQ * EMB / 4 + 255) / 256, 256>>>(qry, Q);
    k_scatter_fused<<<1184, 256>>>(src, dst, ew, emb, E);
    k_readout_mma  <<<(Q + QT - 1) / QT, 128, RM_SMEM>>>(emb, Ws, Wn, bs, bn, Wr, br, qry,
                                                         (float*)d_out, Q);
}

// round 8
// speedup vs baseline: 1.6042x; 1.0317x over previous
#include <cuda_runtime.h>
#include <cstdint>

#define EMB 256
#define HID 64
#define MAXN 100000
#define MAXQ 8192
#define BCAP 64

// ---------------- scratch (device globals; zero-initialized) ----------------
__device__ int   g_slot[MAXN];           // node -> 0 (unmarked) or slot+1; restored to 0 each run
__device__ int   g_qslot[MAXQ];          // query i -> slot (winner index for its node)
__device__ int   g_cnt[MAXQ];            // edges per slot
__device__ int2  g_bin[MAXQ][BCAP];      // (src, w bits) per slot
__device__ float g_s[MAXQ * EMB];        // per-slot sum_e w_e * emb[src_e]
__device__ float g_c[MAXQ];              // per-slot sum_e w_e

// ---------------- k1: mark queried nodes, zero counters ----------------
__global__ void k_mark(const int* __restrict__ query, int Q) {
    int i = blockIdx.x * blockDim.x + threadIdx.x;
    if (i < MAXQ) g_cnt[i] = 0;
    if (i < Q) {
        int node = query[i];
        int old = atomicCAS(&g_slot[node], 0, i + 1);
        g_qslot[i] = (old == 0) ? i : (old - 1);
    }
}

// ---------------- k2: scan edges, bin hits by dst slot ----------------
__global__ void __launch_bounds__(256) k_filter(
    const int* __restrict__ src, const int* __restrict__ dst,
    const float* __restrict__ ew, int E)
{
    int e = blockIdx.x * blockDim.x + threadIdx.x;
    if (e >= E) return;
    int m = g_slot[dst[e]];
    if (m > 0) {
        int sl = m - 1;
        int pos = atomicAdd(&g_cnt[sl], 1);
        if (pos < BCAP) g_bin[sl][pos] = make_int2(src[e], __float_as_int(ew[e]));
    }
}

// ---------------- k3: warp per slot, register accumulate, plain store ----------------
__global__ void __launch_bounds__(256) k_accum(const float* __restrict__ emb) {
    int slot = (blockIdx.x * blockDim.x + threadIdx.x) >> 5;
    int lane = threadIdx.x & 31;
    if (slot >= MAXQ) return;

    int cnt = min(g_cnt[slot], BCAP);
    const int2* bin = g_bin[slot];

    float4 acc0 = make_float4(0.f, 0.f, 0.f, 0.f);
    float4 acc1 = make_float4(0.f, 0.f, 0.f, 0.f);
    float  wsum = 0.f;

    int j = 0;
    for (; j + 2 <= cnt; j += 2) {
        int2 b0 = bin[j], b1 = bin[j + 1];
        float w0 = __int_as_float(b0.y), w1 = __int_as_float(b1.y);
        const float4* r0 = (const float4*)(emb + (size_t)b0.x * EMB);
        const float4* r1 = (const float4*)(emb + (size_t)b1.x * EMB);
        float4 v00 = r0[lane], v01 = r0[lane + 32];
        float4 v10 = r1[lane], v11 = r1[lane + 32];
        acc0.x = fmaf(w0, v00.x, acc0.x); acc0.y = fmaf(w0, v00.y, acc0.y);
        acc0.z = fmaf(w0, v00.z, acc0.z); acc0.w = fmaf(w0, v00.w, acc0.w);
        acc1.x = fmaf(w0, v01.x, acc1.x); acc1.y = fmaf(w0, v01.y, acc1.y);
        acc1.z = fmaf(w0, v01.z, acc1.z); acc1.w = fmaf(w0, v01.w, acc1.w);
        acc0.x = fmaf(w1, v10.x, acc0.x); acc0.y = fmaf(w1, v10.y, acc0.y);
        acc0.z = fmaf(w1, v10.z, acc0.z); acc0.w = fmaf(w1, v10.w, acc0.w);
        acc1.x = fmaf(w1, v11.x, acc1.x); acc1.y = fmaf(w1, v11.y, acc1.y);
        acc1.z = fmaf(w1, v11.z, acc1.z); acc1.w = fmaf(w1, v11.w, acc1.w);
        wsum += w0 + w1;
    }
    if (j < cnt) {
        int2 b0 = bin[j];
        float w0 = __int_as_float(b0.y);
        const float4* r0 = (const float4*)(emb + (size_t)b0.x * EMB);
        float4 v00 = r0[lane], v01 = r0[lane + 32];
        acc0.x = fmaf(w0, v00.x, acc0.x); acc0.y = fmaf(w0, v00.y, acc0.y);
        acc0.z = fmaf(w0, v00.z, acc0.z); acc0.w = fmaf(w0, v00.w, acc0.w);
        acc1.x = fmaf(w0, v01.x, acc1.x); acc1.y = fmaf(w0, v01.y, acc1.y);
        acc1.z = fmaf(w0, v01.z, acc1.z); acc1.w = fmaf(w0, v01.w, acc1.w);
        wsum += w0;
    }

    float4* srow = (float4*)(g_s + (size_t)slot * EMB);
    srow[lane]      = acc0;
    srow[lane + 32] = acc1;
    if (lane == 0) g_c[slot] = wsum;
}

// ---------------- k4: tensor-core readout (+ g_slot restore) ----------------
// out[q] = Wr . relu(Ws@emb[node_q] + Wn@s[slot_q] + bs + c_q*bn) + br
// [16q x 64o] tile, K=512 (chunks 0-3: Ws/emb, 4-7: Wn/g_s), cp.async double
// buffered, mma.sync.m16n8k8.tf32 with cvt.rna. 128 thr, 4 n-warps.
#define QT     16
#define KCH    64
#define AROW   68
#define ABUF   (QT * AROW)              // 1088
#define BBUF   (HID * AROW)             // 4352
#define ASM_O  0
#define BSM_O  (2 * ABUF)
#define AUX_O  (BSM_O + 2 * BBUF)       // nodes[16] slots[16] csm[16] rsum[64]
#define RM_SMEM ((AUX_O + 112) * 4)

__device__ __forceinline__ uint32_t f2tf32(float x) {
    uint32_t r;
    asm("cvt.rna.tf32.f32 %0, %1;" : "=r"(r) : "f"(x));
    return r;
}

__global__ void __launch_bounds__(128) k_readout_mma(
    const float* __restrict__ emb, const float* __restrict__ Ws,
    const float* __restrict__ Wn,  const float* __restrict__ bs,
    const float* __restrict__ bn,  const float* __restrict__ Wr,
    const float* __restrict__ br,  const int* __restrict__ query,
    float* __restrict__ out, int Q)
{
    extern __shared__ float sm[];
    int*   nodes = (int*)(sm + AUX_O);
    int*   slots = nodes + QT;
    float* csm   = (float*)(slots + QT);
    float* rsum  = csm + QT;               // [4][QT]

    int tid   = threadIdx.x;
    int qbase = blockIdx.x * QT;

    if (tid < QT) {
        int q = qbase + tid;
        int node = (q < Q) ? query[q] : query[0];
        int sl   = (q < Q) ? g_qslot[q] : 0;
        nodes[tid] = node;
        slots[tid] = sl;
        csm[tid]   = g_c[sl];
    }
    __syncthreads();

    uint32_t smem_u32;
    asm("{ .reg .u64 t; cvta.to.shared.u64 t, %1; cvt.u32.u64 %0, t; }"
        : "=r"(smem_u32) : "l"(sm));

#define STAGE(C, B) { \
    int kc = ((C) & 3) * KCH; \
    _Pragma("unroll") \
    for (int it = 0; it < 2; ++it) { \
        int idx = tid + it * 128, row = idx >> 4, c4 = idx & 15; \
        const float* rb = ((C) < 4) ? emb + (size_t)nodes[row] * EMB \
                                    : g_s + (size_t)slots[row] * EMB; \
        const float* srcp = rb + kc + c4 * 4; \
        uint32_t dstp = smem_u32 + (uint32_t)(ASM_O + (B) * ABUF + row * AROW + c4 * 4) * 4u; \
        asm volatile("cp.async.cg.shared.global [%0], [%1], 16;" :: "r"(dstp), "l"(srcp)); \
    } \
    const float* W = ((C) < 4) ? Ws : Wn; \
    _Pragma("unroll") \
    for (int it = 0; it < 8; ++it) { \
        int idx = tid + it * 128, o = idx >> 4, c4 = idx & 15; \
        const float* srcp = W + o * EMB + kc + c4 * 4; \
        uint32_t dstp = smem_u32 + (uint32_t)(BSM_O + (B) * BBUF + o * AROW + c4 * 4) * 4u; \
        asm volatile("cp.async.cg.shared.global [%0], [%1], 16;" :: "r"(dstp), "l"(srcp)); \
    } \
    asm volatile("cp.async.commit_group;"); }

    int lane = tid & 31;
    int wn   = tid >> 5;                 // 0..3 : o-range wn*16 .. +15
    int g    = lane >> 2, t = lane & 3;

    float acc[2][4];
#pragma unroll
    for (int a = 0; a < 2; ++a)
#pragma unroll
        for (int b = 0; b < 4; ++b) acc[a][b] = 0.f;

    STAGE(0, 0)

#pragma unroll
    for (int c = 0; c < 8; ++c) {
        if (c < 7) STAGE(c + 1, (c + 1) & 1)
        if (c < 7) { asm volatile("cp.async.wait_group 1;"); }
        else       { asm volatile("cp.async.wait_group 0;"); }
        __syncthreads();

        const float* ab = sm + ASM_O + (c & 1) * ABUF + g * AROW + t;
        const float* bb = sm + BSM_O + (c & 1) * BBUF + (wn * 16 + g) * AROW + t;
#pragma unroll
        for (int ks = 0; ks < 8; ++ks) {
            int k0 = ks * 8;
            uint32_t a0 = f2tf32(ab[k0]);
            uint32_t a1 = f2tf32(ab[k0 + 8 * AROW]);
            uint32_t a2 = f2tf32(ab[k0 + 4]);
            uint32_t a3 = f2tf32(ab[k0 + 8 * AROW + 4]);
#pragma unroll
            for (int nt = 0; nt < 2; ++nt) {
                uint32_t b0 = f2tf32(bb[k0 + nt * 8 * AROW]);
                uint32_t b1 = f2tf32(bb[k0 + nt * 8 * AROW + 4]);
                asm("mma.sync.aligned.m16n8k8.row.col.f32.tf32.tf32.f32 "
                    "{%0,%1,%2,%3}, {%4,%5,%6,%7}, {%8,%9}, {%0,%1,%2,%3};"
                    : "+f"(acc[nt][0]), "+f"(acc[nt][1]),
                      "+f"(acc[nt][2]), "+f"(acc[nt][3])
                    : "r"(a0), "r"(a1), "r"(a2), "r"(a3), "r"(b0), "r"(b1));
            }
        }
        __syncthreads();
    }

    // Epilogue: rows q = g, g+8 ; cols o = wn*16 + nt*8 + 2t (+1)
    int qr0 = g, qr1 = g + 8;
    float cc0 = csm[qr0], cc1 = csm[qr1];
    float l0 = 0.f, l1 = 0.f;
#pragma unroll
    for (int nt = 0; nt < 2; ++nt) {
        int o0 = wn * 16 + nt * 8 + 2 * t;
        float b_s0 = bs[o0], b_s1 = bs[o0 + 1];
        float b_n0 = bn[o0], b_n1 = bn[o0 + 1];
        float w_r0 = Wr[o0], w_r1 = Wr[o0 + 1];
        l0 += w_r0 * fmaxf(acc[nt][0] + b_s0 + cc0 * b_n0, 0.f)
            + w_r1 * fmaxf(acc[nt][1] + b_s1 + cc0 * b_n1, 0.f);
        l1 += w_r0 * fmaxf(acc[nt][2] + b_s0 + cc1 * b_n0, 0.f)
            + w_r1 * fmaxf(acc[nt][3] + b_s1 + cc1 * b_n1, 0.f);
    }
    l0 += __shfl_xor_sync(0xffffffffu, l0, 1);
    l0 += __shfl_xor_sync(0xffffffffu, l0, 2);
    l1 += __shfl_xor_sync(0xffffffffu, l1, 1);
    l1 += __shfl_xor_sync(0xffffffffu, l1, 2);
    if (t == 0) {
        rsum[wn * QT + qr0] = l0;
        rsum[wn * QT + qr1] = l1;
    }
    __syncthreads();
    if (tid < QT) {
        int q = qbase + tid;
        if (q < Q) {
            out[q] = rsum[tid] + rsum[QT + tid] + rsum[2 * QT + tid]
                   + rsum[3 * QT + tid] + br[0];
            g_slot[nodes[tid]] = 0;   // restore for next replay (idempotent)
        }
    }
}

// ---------------- launch ----------------
extern "C" void kernel_launch(void* const* d_in, const int* in_sizes, int n_in,
                              void* d_out, int out_size) {
    const float* emb = (const float*)d_in[0];
    const float* ew  = (const float*)d_in[1];
    const float* Ws  = (const float*)d_in[2];
    const float* bs  = (const float*)d_in[3];
    const float* Wn  = (const float*)d_in[4];
    const float* bn  = (const float*)d_in[5];
    const float* Wr  = (const float*)d_in[6];
    const float* br  = (const float*)d_in[7];
    const int*   src = (const int*)d_in[8];
    const int*   dst = (const int*)d_in[9];
    const int*   qry = (const int*)d_in[10];

    int E = in_sizes[8];
    int Q = in_sizes[10];

    cudaFuncSetAttribute(k_readout_mma, cudaFuncAttributeMaxDynamicSharedMemorySize, RM_SMEM);

    k_mark       <<<(MAXQ + 255) / 256, 256>>>(qry, Q);
    k_filter     <<<(E + 255) / 256, 256>>>(src, dst, ew, E);
    k_accum      <<<(MAXQ * 32 + 255) / 256, 256>>>(emb);
    k_readout_mma<<<(Q + QT - 1) / QT, 128, RM_SMEM>>>(emb, Ws, Wn, bs, bn, Wr, br, qry,
                                                       (float*)d_out, Q);
}

// round 9
// speedup vs baseline: 1.7181x; 1.0710x over previous
#include <cuda_runtime.h>
#include <cstdint>

#define EMB 256
#define HID 64
#define MAXN 100000
#define MAXQ 8192
#define BCAP 64

// ---------------- scratch (device globals; zero-initialized) ----------------
__device__ int   g_slot[MAXN];           // node -> 0 (unmarked) or slot+1; restored each run
__device__ int   g_qslot[MAXQ];          // query i -> slot (winner index for its node)
__device__ int   g_cnt[MAXQ];            // edges per slot
__device__ int2  g_bin[MAXQ][BCAP];      // (src, w bits) per slot
__device__ float g_s[MAXQ * EMB];        // per-slot sum_e w_e * emb[src_e]
__device__ float g_c[MAXQ];              // per-slot sum_e w_e

// ---------------- k1: mark queried nodes, zero counters ----------------
__global__ void k_mark(const int* __restrict__ query, int Q) {
    int i = blockIdx.x * blockDim.x + threadIdx.x;
    if (i < MAXQ) g_cnt[i] = 0;
    if (i < Q) {
        int node = query[i];
        int old = atomicCAS(&g_slot[node], 0, i + 1);
        g_qslot[i] = (old == 0) ? i : (old - 1);
    }
}

// ---------------- k2: scan edges, bin hits by dst slot ----------------
__global__ void __launch_bounds__(256) k_filter(
    const int* __restrict__ src, const int* __restrict__ dst,
    const float* __restrict__ ew, int E)
{
    int e = blockIdx.x * blockDim.x + threadIdx.x;
    if (e >= E) return;
    int m = g_slot[dst[e]];
    if (m > 0) {
        int sl = m - 1;
        int pos = atomicAdd(&g_cnt[sl], 1);
        if (pos < BCAP) g_bin[sl][pos] = make_int2(src[e], __float_as_int(ew[e]));
    }
}

// ---------------- k3: warp per slot, register accumulate, plain store ----------------
__global__ void __launch_bounds__(256) k_accum(const float* __restrict__ emb) {
    int slot = (blockIdx.x * blockDim.x + threadIdx.x) >> 5;
    int lane = threadIdx.x & 31;
    if (slot >= MAXQ) return;

    int cnt = min(g_cnt[slot], BCAP);
    const int2* bin = g_bin[slot];

    float4 acc0 = make_float4(0.f, 0.f, 0.f, 0.f);
    float4 acc1 = make_float4(0.f, 0.f, 0.f, 0.f);
    float  wsum = 0.f;

    int j = 0;
    for (; j + 2 <= cnt; j += 2) {
        int2 b0 = bin[j], b1 = bin[j + 1];
        float w0 = __int_as_float(b0.y), w1 = __int_as_float(b1.y);
        const float4* r0 = (const float4*)(emb + (size_t)b0.x * EMB);
        const float4* r1 = (const float4*)(emb + (size_t)b1.x * EMB);
        float4 v00 = r0[lane], v01 = r0[lane + 32];
        float4 v10 = r1[lane], v11 = r1[lane + 32];
        acc0.x = fmaf(w0, v00.x, acc0.x); acc0.y = fmaf(w0, v00.y, acc0.y);
        acc0.z = fmaf(w0, v00.z, acc0.z); acc0.w = fmaf(w0, v00.w, acc0.w);
        acc1.x = fmaf(w0, v01.x, acc1.x); acc1.y = fmaf(w0, v01.y, acc1.y);
        acc1.z = fmaf(w0, v01.z, acc1.z); acc1.w = fmaf(w0, v01.w, acc1.w);
        acc0.x = fmaf(w1, v10.x, acc0.x); acc0.y = fmaf(w1, v10.y, acc0.y);
        acc0.z = fmaf(w1, v10.z, acc0.z); acc0.w = fmaf(w1, v10.w, acc0.w);
        acc1.x = fmaf(w1, v11.x, acc1.x); acc1.y = fmaf(w1, v11.y, acc1.y);
        acc1.z = fmaf(w1, v11.z, acc1.z); acc1.w = fmaf(w1, v11.w, acc1.w);
        wsum += w0 + w1;
    }
    if (j < cnt) {
        int2 b0 = bin[j];
        float w0 = __int_as_float(b0.y);
        const float4* r0 = (const float4*)(emb + (size_t)b0.x * EMB);
        float4 v00 = r0[lane], v01 = r0[lane + 32];
        acc0.x = fmaf(w0, v00.x, acc0.x); acc0.y = fmaf(w0, v00.y, acc0.y);
        acc0.z = fmaf(w0, v00.z, acc0.z); acc0.w = fmaf(w0, v00.w, acc0.w);
        acc1.x = fmaf(w0, v01.x, acc1.x); acc1.y = fmaf(w0, v01.y, acc1.y);
        acc1.z = fmaf(w0, v01.z, acc1.z); acc1.w = fmaf(w0, v01.w, acc1.w);
        wsum += w0;
    }

    float4* srow = (float4*)(g_s + (size_t)slot * EMB);
    srow[lane]      = acc0;
    srow[lane + 32] = acc1;
    if (lane == 0) g_c[slot] = wsum;
}

// ---------------- k4: tensor-core readout (+ g_slot restore) ----------------
// out[q] = Wr . relu(Ws@emb[node_q] + Wn@s[slot_q] + bs + c_q*bn) + br
// [32q x 64o] tile, K=512 (chunks 0-3: Ws/emb, 4-7: Wn/g_s), cp.async double
// buffered, mma.sync.m16n8k8.tf32 with cvt.rna. 256 thr = 8 warps,
// warp tile m16 x n16 (wm 0..1, wn 0..3).
#define QT     32
#define KCH    64
#define AROW   68
#define ABUF   (QT * AROW)              // 2176
#define BBUF   (HID * AROW)             // 4352
#define ASM_O  0
#define BSM_O  (2 * ABUF)
#define AUX_O  (BSM_O + 2 * BBUF)       // nodes[32] slots[32] csm[32] rsum[4][32]
#define RM_SMEM ((AUX_O + 224) * 4)

__device__ __forceinline__ uint32_t f2tf32(float x) {
    uint32_t r;
    asm("cvt.rna.tf32.f32 %0, %1;" : "=r"(r) : "f"(x));
    return r;
}

__global__ void __launch_bounds__(256) k_readout_mma(
    const float* __restrict__ emb, const float* __restrict__ Ws,
    const float* __restrict__ Wn,  const float* __restrict__ bs,
    const float* __restrict__ bn,  const float* __restrict__ Wr,
    const float* __restrict__ br,  const int* __restrict__ query,
    float* __restrict__ out, int Q)
{
    extern __shared__ float sm[];
    int*   nodes = (int*)(sm + AUX_O);
    int*   slots = nodes + QT;
    float* csm   = (float*)(slots + QT);
    float* rsum  = csm + QT;               // [4][QT]

    int tid   = threadIdx.x;
    int qbase = blockIdx.x * QT;

    if (tid < QT) {
        int q = qbase + tid;
        int node = (q < Q) ? query[q] : query[0];
        int sl   = (q < Q) ? g_qslot[q] : 0;
        nodes[tid] = node;
        slots[tid] = sl;
        csm[tid]   = g_c[sl];
    }
    __syncthreads();

    uint32_t smem_u32;
    asm("{ .reg .u64 t; cvta.to.shared.u64 t, %1; cvt.u32.u64 %0, t; }"
        : "=r"(smem_u32) : "l"(sm));

#define STAGE(C, B) { \
    int kc = ((C) & 3) * KCH; \
    _Pragma("unroll") \
    for (int it = 0; it < 2; ++it) { \
        int idx = tid + it * 256, row = idx >> 4, c4 = idx & 15; \
        const float* rb = ((C) < 4) ? emb + (size_t)nodes[row] * EMB \
                                    : g_s + (size_t)slots[row] * EMB; \
        const float* srcp = rb + kc + c4 * 4; \
        uint32_t dstp = smem_u32 + (uint32_t)(ASM_O + (B) * ABUF + row * AROW + c4 * 4) * 4u; \
        asm volatile("cp.async.cg.shared.global [%0], [%1], 16;" :: "r"(dstp), "l"(srcp)); \
    } \
    const float* W = ((C) < 4) ? Ws : Wn; \
    _Pragma("unroll") \
    for (int it = 0; it < 4; ++it) { \
        int idx = tid + it * 256, o = idx >> 4, c4 = idx & 15; \
        const float* srcp = W + o * EMB + kc + c4 * 4; \
        uint32_t dstp = smem_u32 + (uint32_t)(BSM_O + (B) * BBUF + o * AROW + c4 * 4) * 4u; \
        asm volatile("cp.async.cg.shared.global [%0], [%1], 16;" :: "r"(dstp), "l"(srcp)); \
    } \
    asm volatile("cp.async.commit_group;"); }

    int lane = tid & 31;
    int w    = tid >> 5;
    int wm   = w >> 2;                   // 0..1 : q-range wm*16 .. +15
    int wn   = w & 3;                    // 0..3 : o-range wn*16 .. +15
    int g    = lane >> 2, t = lane & 3;

    float acc[2][4];
#pragma unroll
    for (int a = 0; a < 2; ++a)
#pragma unroll
        for (int b = 0; b < 4; ++b) acc[a][b] = 0.f;

    STAGE(0, 0)

#pragma unroll
    for (int c = 0; c < 8; ++c) {
        if (c < 7) STAGE(c + 1, (c + 1) & 1)
        if (c < 7) { asm volatile("cp.async.wait_group 1;"); }
        else       { asm volatile("cp.async.wait_group 0;"); }
        __syncthreads();

        const float* ab = sm + ASM_O + (c & 1) * ABUF + (wm * 16 + g) * AROW + t;
        const float* bb = sm + BSM_O + (c & 1) * BBUF + (wn * 16 + g) * AROW + t;
#pragma unroll
        for (int ks = 0; ks < 8; ++ks) {
            int k0 = ks * 8;
            uint32_t a0 = f2tf32(ab[k0]);
            uint32_t a1 = f2tf32(ab[k0 + 8 * AROW]);
            uint32_t a2 = f2tf32(ab[k0 + 4]);
            uint32_t a3 = f2tf32(ab[k0 + 8 * AROW + 4]);
#pragma unroll
            for (int nt = 0; nt < 2; ++nt) {
                uint32_t b0 = f2tf32(bb[k0 + nt * 8 * AROW]);
                uint32_t b1 = f2tf32(bb[k0 + nt * 8 * AROW + 4]);
                asm("mma.sync.aligned.m16n8k8.row.col.f32.tf32.tf32.f32 "
                    "{%0,%1,%2,%3}, {%4,%5,%6,%7}, {%8,%9}, {%0,%1,%2,%3};"
                    : "+f"(acc[nt][0]), "+f"(acc[nt][1]),
                      "+f"(acc[nt][2]), "+f"(acc[nt][3])
                    : "r"(a0), "r"(a1), "r"(a2), "r"(a3), "r"(b0), "r"(b1));
            }
        }
        __syncthreads();
    }

    // Epilogue: rows q = wm*16+g (+8); cols o = wn*16 + nt*8 + 2t (+1)
    int qr0 = wm * 16 + g, qr1 = qr0 + 8;
    float cc0 = csm[qr0], cc1 = csm[qr1];
    float l0 = 0.f, l1 = 0.f;
#pragma unroll
    for (int nt = 0; nt < 2; ++nt) {
        int o0 = wn * 16 + nt * 8 + 2 * t;
        float b_s0 = bs[o0], b_s1 = bs[o0 + 1];
        float b_n0 = bn[o0], b_n1 = bn[o0 + 1];
        float w_r0 = Wr[o0], w_r1 = Wr[o0 + 1];
        l0 += w_r0 * fmaxf(acc[nt][0] + b_s0 + cc0 * b_n0, 0.f)
            + w_r1 * fmaxf(acc[nt][1] + b_s1 + cc0 * b_n1, 0.f);
        l1 += w_r0 * fmaxf(acc[nt][2] + b_s0 + cc1 * b_n0, 0.f)
            + w_r1 * fmaxf(acc[nt][3] + b_s1 + cc1 * b_n1, 0.f);
    }
    l0 += __shfl_xor_sync(0xffffffffu, l0, 1);
    l0 += __shfl_xor_sync(0xffffffffu, l0, 2);
    l1 += __shfl_xor_sync(0xffffffffu, l1, 1);
    l1 += __shfl_xor_sync(0xffffffffu, l1, 2);
    if (t == 0) {
        rsum[wn * QT + qr0] = l0;
        rsum[wn * QT + qr1] = l1;
    }
    __syncthreads();
    if (tid < QT) {
        int q = qbase + tid;
        if (q < Q) {
            out[q] = rsum[tid] + rsum[QT + tid] + rsum[2 * QT + tid]
                   + rsum[3 * QT + tid] + br[0];
            g_slot[nodes[tid]] = 0;   // restore for next replay (idempotent)
        }
    }
}

// ---------------- launch ----------------
extern "C" void kernel_launch(void* const* d_in, const int* in_sizes, int n_in,
                              void* d_out, int out_size) {
    const float* emb = (const float*)d_in[0];
    const float* ew  = (const float*)d_in[1];
    const float* Ws  = (const float*)d_in[2];
    const float* bs  = (const float*)d_in[3];
    const float* Wn  = (const float*)d_in[4];
    const float* bn  = (const float*)d_in[5];
    const float* Wr  = (const float*)d_in[6];
    const float* br  = (const float*)d_in[7];
    const int*   src = (const int*)d_in[8];
    const int*   dst = (const int*)d_in[9];
    const int*   qry = (const int*)d_in[10];

    int E = in_sizes[8];
    int Q = in_sizes[10];

    cudaFuncSetAttribute(k_readout_mma, cudaFuncAttributeMaxDynamicSharedMemorySize, RM_SMEM);

    k_mark       <<<(MAXQ + 255) / 256, 256>>>(qry, Q);
    k_filter     <<<(E + 255) / 256, 256>>>(src, dst, ew, E);
    k_accum      <<<(MAXQ * 32 + 255) / 256, 256>>>(emb);
    k_readout_mma<<<(Q + QT - 1) / QT, 256, RM_SMEM>>>(emb, Ws, Wn, bs, bn, Wr, br, qry,
                                                       (float*)d_out, Q);
}